// round 17
// baseline (speedup 1.0000x reference)
#include <cuda_runtime.h>
#include <cuda_bf16.h>
#include <stdint.h>
#include <math.h>

typedef unsigned int u32;

#define B_   32
#define W_   50
#define H_   192
#define H4   768
#define V_   32000
#define TD   49
#define ROWS 1568   // TD * B_
#define MPAD 1664   // 13 * 128

// ---------------- device scratch ----------------
__device__ float g_xf[1600*H4];         // enc fwd pre:  emb@Wf + bf   (t*32+b, n)
__device__ float g_xb[1600*H4];         // enc bwd pre
__device__ float g_xd[ROWS*H4];         // dec pre:      demb@Wd[0:192] + bd
__device__ float g_outs_f[W_*B_*H_];
__device__ float g_outs_b[W_*B_*H_];
__device__ float g_hfin[2][B_*H_], g_cfin[2][B_*H_];
__device__ float g_hcat[MPAD*384];      // [h(0:192)|c_t(192:384)]; pad rows never stored by GEMM
__device__ float g_betas[TD*B_*W_];
__device__ float g_gate[TD*B_];
__device__ __align__(16) __nv_bfloat16 g_wh[384*V_];   // Wdense hi
__device__ __align__(16) __nv_bfloat16 g_wl[384*V_];   // Wdense lo
__device__ __align__(16) __nv_bfloat16 g_ah[MPAD*384]; // hcat hi
__device__ __align__(16) __nv_bfloat16 g_al[MPAD*384]; // hcat lo

__device__ __forceinline__ float sigf(float x){ return 1.0f/(1.0f + expf(-x)); }

__device__ __forceinline__ void split2(float x, float y, u32& hi, u32& lo) {
    __nv_bfloat162 h2 = __floats2bfloat162_rn(x, y);
    float hx = __bfloat162float(h2.x);
    float hy = __bfloat162float(h2.y);
    __nv_bfloat162 l2 = __floats2bfloat162_rn(x - hx, y - hy);
    hi = *(u32*)&h2; lo = *(u32*)&l2;
}

// ---------------- fused pre-GEMM: [enc@Wf | enc@Wb | dec@Wd_top] ----------------
__global__ void __launch_bounds__(256) k_pre(const int* __restrict__ enc_in,
                                             const int* __restrict__ dec_in,
                                             const float* __restrict__ emb,
                                             const float* __restrict__ Wf, const float* __restrict__ bfv,
                                             const float* __restrict__ Wb, const float* __restrict__ bbv,
                                             const float* __restrict__ Wd, const float* __restrict__ bdv) {
    __shared__ float As[192*16];   // [k][r]
    __shared__ float Bs[16*128];   // [r][c]
    int row0 = blockIdx.x * 16;
    int which = (row0 < 1600) ? 0 : (row0 < 3200) ? 1 : 2;
    const int*   toks = (which == 2) ? dec_in : enc_in;
    const float* Wm   = (which == 0) ? Wf : (which == 1) ? Wb : Wd;
    const float* bias = (which == 0) ? bfv : (which == 1) ? bbv : bdv;
    float* outp = (which == 0) ? g_xf : (which == 1) ? g_xb : g_xd;
    int lr0  = row0 - which * 1600;
    int col0 = blockIdx.y * 128;
    int tid = threadIdx.x;

    for (int i = tid; i < 16*192; i += 256) {
        int r = i / 192, k = i % 192;
        int lr = lr0 + r;
        int tok = toks[(lr & 31) * W_ + (lr >> 5)];
        As[k*16 + r] = emb[tok*H_ + k];
    }
    int tx = tid & 31, ty = tid >> 5;
    float a0c[4] = {0,0,0,0}, a1c[4] = {0,0,0,0};
    for (int k0 = 0; k0 < 192; k0 += 16) {
        __syncthreads();
        for (int i = tid; i < 16*128; i += 256) {
            int r = i >> 7, c = i & 127;
            Bs[i] = Wm[(size_t)(k0 + r)*H4 + col0 + c];
        }
        __syncthreads();
        #pragma unroll
        for (int kk = 0; kk < 16; kk++) {
            float a0 = As[(k0+kk)*16 + ty];
            float a1 = As[(k0+kk)*16 + ty + 8];
            float4 w = *(float4*)&Bs[kk*128 + tx*4];
            a0c[0] = fmaf(a0,w.x,a0c[0]); a0c[1] = fmaf(a0,w.y,a0c[1]);
            a0c[2] = fmaf(a0,w.z,a0c[2]); a0c[3] = fmaf(a0,w.w,a0c[3]);
            a1c[0] = fmaf(a1,w.x,a1c[0]); a1c[1] = fmaf(a1,w.y,a1c[1]);
            a1c[2] = fmaf(a1,w.z,a1c[2]); a1c[3] = fmaf(a1,w.w,a1c[3]);
        }
    }
    float4 b4 = *(const float4*)(bias + col0 + tx*4);
    float4 o;
    o.x = a0c[0]+b4.x; o.y = a0c[1]+b4.y; o.z = a0c[2]+b4.z; o.w = a0c[3]+b4.w;
    *(float4*)(outp + (size_t)(lr0 + ty)*H4 + col0 + tx*4) = o;
    o.x = a1c[0]+b4.x; o.y = a1c[1]+b4.y; o.z = a1c[2]+b4.z; o.w = a1c[3]+b4.w;
    *(float4*)(outp + (size_t)(lr0 + ty + 8)*H4 + col0 + tx*4) = o;
}

// ---------------- encoder: 64 CTAs (dir x batch), batch-independent, zero syncs ----------------
__global__ void __launch_bounds__(192) k_enc(const float* __restrict__ Uf,
                                             const float* __restrict__ Ub) {
    __shared__ float hs[192];
    __shared__ float zsm[768];
    int cta = blockIdx.x;
    int dir = cta >> 5;
    int b   = cta & 31;
    const float4* U4   = (const float4*)(dir ? Ub : Uf);
    const float*  xpre = dir ? g_xb : g_xf;
    float* outs = dir ? g_outs_b : g_outs_f;
    int tid = threadIdx.x;
    hs[tid] = 0.f;
    float c_reg = 0.f;
    __syncthreads();

    for (int s = 0; s < W_; s++) {
        int t = dir ? (W_ - 1 - s) : s;
        float4 acc = *(const float4*)(xpre + (size_t)(t*B_ + b)*H4 + tid*4);
        const float4* ucol = U4 + tid;
        #pragma unroll 4
        for (int k = 0; k < 192; k++) {
            float hv = hs[k];
            float4 w = ucol[k*192];
            acc.x = fmaf(hv,w.x,acc.x); acc.y = fmaf(hv,w.y,acc.y);
            acc.z = fmaf(hv,w.z,acc.z); acc.w = fmaf(hv,w.w,acc.w);
        }
        *(float4*)(zsm + tid*4) = acc;
        __syncthreads();
        float zi = zsm[tid], zf = zsm[192+tid], zg = zsm[384+tid], zo = zsm[576+tid];
        float cn = sigf(zf)*c_reg + sigf(zi)*tanhf(zg);
        float hn = sigf(zo)*tanhf(cn);
        c_reg = cn;
        hs[tid] = hn;
        outs[(t*B_ + b)*H_ + tid] = hn;
        __syncthreads();
    }
    g_hfin[dir][b*H_ + tid] = hs[tid];
    g_cfin[dir][b*H_ + tid] = c_reg;
}

// ---------------- decoder: 32 CTAs (one per batch), zero syncs ----------------
__global__ void __launch_bounds__(192) k_dec(const float* __restrict__ Wq,
                                             const float* __restrict__ sentinel,
                                             const float* __restrict__ a_bias,
                                             const float* __restrict__ Ud,
                                             const float* __restrict__ Wd) {
    extern __shared__ float dsm[];
    float* wq   = dsm;            // 192*192 = 36864 floats
    float* fatt = dsm + 36864;    // 51*192  = 9792 floats
    __shared__ float hs[192], cts[192], q[192], zsm[768], sc[64];
    int b = blockIdx.x;
    int tid = threadIdx.x;

    for (int i = tid; i < 192*192; i += 192) wq[i] = Wq[i];
    for (int i = tid; i < W_*H_; i += 192) {
        int w = i / H_, k = i % H_;
        fatt[i] = g_outs_f[(w*B_ + b)*H_ + k] + g_outs_b[(w*B_ + b)*H_ + k];
    }
    fatt[W_*H_ + tid] = sentinel[tid];
    hs[tid] = g_hfin[0][b*H_ + tid] + g_hfin[1][b*H_ + tid];
    float c_reg = g_cfin[0][b*H_ + tid] + g_cfin[1][b*H_ + tid];
    const float4* Ud4  = (const float4*)Ud;
    const float4* Wd24 = (const float4*)(Wd + 192*H4);
    __syncthreads();

    for (int t = 0; t < TD; t++) {
        // q = h @ Wq (h = previous hidden)
        {
            float a = 0.f;
            #pragma unroll 8
            for (int k = 0; k < 192; k++) a = fmaf(hs[k], wq[k*192 + tid], a);
            q[tid] = a;
        }
        __syncthreads();
        int warp = tid >> 5, lane = tid & 31;
        for (int j = warp; j < 51; j += 6) {
            float s = 0.f;
            for (int k = lane; k < 192; k += 32) s += tanhf(fatt[j*192 + k] * q[k]);
            #pragma unroll
            for (int off = 16; off; off >>= 1) s += __shfl_xor_sync(0xffffffffu, s, off);
            if (lane == 0) sc[j] = s + a_bias[t*(W_+1) + j];
        }
        __syncthreads();
        if (tid < 32) {
            float v0 = sc[tid];
            float v1 = (tid + 32 < 51) ? sc[tid + 32] : -1e30f;
            float m = fmaxf(v0, v1);
            #pragma unroll
            for (int off = 16; off; off >>= 1) m = fmaxf(m, __shfl_xor_sync(0xffffffffu, m, off));
            float e0 = expf(v0 - m);
            float e1 = (tid + 32 < 51) ? expf(v1 - m) : 0.f;
            float s = e0 + e1;
            #pragma unroll
            for (int off = 16; off; off >>= 1) s += __shfl_xor_sync(0xffffffffu, s, off);
            float inv = 1.f / s;
            sc[tid] = e0 * inv;
            if (tid + 32 < 51) sc[tid + 32] = e1 * inv;
        }
        __syncthreads();
        if (tid < W_) g_betas[(t*B_ + b)*W_ + tid] = sc[tid];
        if (tid == W_) g_gate[t*B_ + b] = sc[W_];
        {
            float a2 = 0.f;
            #pragma unroll
            for (int w = 0; w < W_; w++) a2 = fmaf(fatt[w*192 + tid], sc[w], a2);
            cts[tid] = a2;
            g_hcat[(size_t)(t*B_ + b)*384 + 192 + tid] = a2;
        }
        __syncthreads();
        // cell: z = xd + h@Ud + c_t@Wd2
        float4 acc = *(const float4*)(g_xd + (size_t)(t*B_ + b)*H4 + tid*4);
        const float4* uc = Ud4 + tid;
        const float4* wc = Wd24 + tid;
        #pragma unroll 4
        for (int k = 0; k < 192; k++) {
            float hv = hs[k];
            float4 w = uc[k*192];
            acc.x = fmaf(hv,w.x,acc.x); acc.y = fmaf(hv,w.y,acc.y);
            acc.z = fmaf(hv,w.z,acc.z); acc.w = fmaf(hv,w.w,acc.w);
        }
        #pragma unroll 4
        for (int k = 0; k < 192; k++) {
            float cv = cts[k];
            float4 w = wc[k*192];
            acc.x = fmaf(cv,w.x,acc.x); acc.y = fmaf(cv,w.y,acc.y);
            acc.z = fmaf(cv,w.z,acc.z); acc.w = fmaf(cv,w.w,acc.w);
        }
        *(float4*)(zsm + tid*4) = acc;
        __syncthreads();
        float zi = zsm[tid], zf = zsm[192+tid], zg = zsm[384+tid], zo = zsm[576+tid];
        float cn = sigf(zf)*c_reg + sigf(zi)*tanhf(zg);
        float hn = sigf(zo)*tanhf(cn);
        c_reg = cn;
        hs[tid] = hn;
        g_hcat[(size_t)(t*B_ + b)*384 + tid] = hn;
        __syncthreads();
    }
}

// ---------------- pre-split kernels: fp32 -> bf16 hi/lo ----------------
__global__ void __launch_bounds__(256) k_split_w(const float* __restrict__ W) {
    int idx = blockIdx.x * 256 + threadIdx.x;          // float4 index, 3,072,000 total
    float4 v = ((const float4*)W)[idx];
    u32 h0, l0, h1, l1;
    split2(v.x, v.y, h0, l0);
    split2(v.z, v.w, h1, l1);
    ((u32*)g_wh)[idx*2]   = h0; ((u32*)g_wh)[idx*2+1] = h1;
    ((u32*)g_wl)[idx*2]   = l0; ((u32*)g_wl)[idx*2+1] = l1;
}
__global__ void __launch_bounds__(256) k_split_a() {
    int idx = blockIdx.x * 256 + threadIdx.x;          // float4 index, 159,744 total
    float4 v = ((const float4*)g_hcat)[idx];
    u32 h0, l0, h1, l1;
    split2(v.x, v.y, h0, l0);
    split2(v.z, v.w, h1, l1);
    ((u32*)g_ah)[idx*2]   = h0; ((u32*)g_ah)[idx*2+1] = h1;
    ((u32*)g_al)[idx*2]   = l0; ((u32*)g_al)[idx*2+1] = l1;
}

// ---------------- pipelined tensor-core GEMM ----------------
#define ASTR 72    // A smem row stride (bf16), 144B
#define BSTR 136   // B smem row stride (bf16), 272B
// smem byte layout: AsHi 0, AsLo 18432, buf0Hi 36864, buf0Lo 54272, buf1Hi 71680, buf1Lo 89088; total 106496

#define CP16(dst, src) asm volatile("cp.async.cg.shared.global [%0], [%1], 16;\n" :: "r"(dst), "l"(src))
#define CPCOMMIT()     asm volatile("cp.async.commit_group;\n" ::: "memory")
#define CPWAIT(n)      asm volatile("cp.async.wait_group %0;\n" :: "n"(n) : "memory")

__device__ __forceinline__ void ldmx4(u32* r, u32 addr) {
    asm volatile("ldmatrix.sync.aligned.m8n8.x4.shared.b16 {%0,%1,%2,%3}, [%4];"
                 : "=r"(r[0]), "=r"(r[1]), "=r"(r[2]), "=r"(r[3]) : "r"(addr));
}
__device__ __forceinline__ void ldmx4t(u32* r, u32 addr) {
    asm volatile("ldmatrix.sync.aligned.m8n8.x4.trans.shared.b16 {%0,%1,%2,%3}, [%4];"
                 : "=r"(r[0]), "=r"(r[1]), "=r"(r[2]), "=r"(r[3]) : "r"(addr));
}
__device__ __forceinline__ void mma16816(float* d, const u32* a, u32 b0, u32 b1) {
    asm volatile("mma.sync.aligned.m16n8k16.row.col.f32.bf16.bf16.f32 "
                 "{%0,%1,%2,%3},{%4,%5,%6,%7},{%8,%9},{%0,%1,%2,%3};"
                 : "+f"(d[0]), "+f"(d[1]), "+f"(d[2]), "+f"(d[3])
                 : "r"(a[0]), "r"(a[1]), "r"(a[2]), "r"(a[3]), "r"(b0), "r"(b1));
}

__global__ void __launch_bounds__(256, 2) k_tc_gemm(const float* __restrict__ bdense,
                                                    float* __restrict__ out) {
    extern __shared__ unsigned char gsm[];
    u32 sb = (u32)__cvta_generic_to_shared(gsm);
    const u32 sAhi = sb;
    u32 bufHi[2]; bufHi[0] = sb + 36864; bufHi[1] = sb + 71680;

    int n0 = blockIdx.x * 128;
    int m0 = blockIdx.y * 128;
    int tid  = threadIdx.x;
    int lane = tid & 31;
    int wid  = tid >> 5;
    int wm = wid & 3;
    int wn = wid >> 2;
    int g   = lane >> 2;
    int tig = lane & 3;

    u32 aRow = (u32)(wm*32 + (lane & 15));
    u32 aColOff = (u32)((lane >> 4) * 8);
    u32 bK = (u32)(lane & 15);
    u32 bN = (u32)(wn*64 + (lane >> 4) * 8);

    float acc[64];
    #pragma unroll
    for (int i = 0; i < 64; i++) acc[i] = 0.f;

    auto issueB = [&](int k0, int buf) {
        u32 hidst = bufHi[buf];
        #pragma unroll
        for (int j = 0; j < 4; j++) {
            int i = tid + j*256;
            int kr = i >> 4, cs = (i & 15) * 8;
            const __nv_bfloat16* srcH = g_wh + (size_t)(k0 + kr)*V_ + n0 + cs;
            const __nv_bfloat16* srcL = g_wl + (size_t)(k0 + kr)*V_ + n0 + cs;
            u32 d = hidst + (u32)(kr*BSTR + cs)*2;
            CP16(d, srcH);
            CP16(d + 17408u, srcL);
        }
    };
    auto issueA = [&](int k0) {
        #pragma unroll
        for (int j = 0; j < 4; j++) {
            int i = tid + j*256;
            int r = i >> 3, cs = (i & 7) * 8;
            const __nv_bfloat16* srcH = g_ah + (size_t)(m0 + r)*384 + k0 + cs;
            const __nv_bfloat16* srcL = g_al + (size_t)(m0 + r)*384 + k0 + cs;
            u32 d = sAhi + (u32)(r*ASTR + cs)*2;
            CP16(d, srcH);
            CP16(d + 18432u, srcL);
        }
    };

    issueB(0, 0); CPCOMMIT();

    for (int c = 0; c < 6; c++) {
        int k0 = c * 64;
        __syncthreads();                 // prior compute done: safe to refill As / next B buffer
        issueA(k0); CPCOMMIT();
        if (c < 5) { issueB(k0 + 64, (c + 1) & 1); CPCOMMIT(); CPWAIT(1); }
        else       { CPWAIT(0); }
        __syncthreads();

        u32 sBhi = bufHi[c & 1], sBlo = sBhi + 17408u;
        u32 sAlo = sAhi + 18432u;

        #pragma unroll
        for (int ks = 0; ks < 4; ks++) {
            u32 ah[2][4], al[2][4];
            #pragma unroll
            for (int mf = 0; mf < 2; mf++) {
                u32 off = ((aRow + mf*16)*ASTR + ks*16 + aColOff) * 2;
                ldmx4(ah[mf], sAhi + off);
                ldmx4(al[mf], sAlo + off);
            }
            #pragma unroll
            for (int nf2 = 0; nf2 < 4; nf2++) {
                u32 boff = ((ks*16 + bK)*BSTR + bN + nf2*16) * 2;
                u32 bh[4], bl[4];
                ldmx4t(bh, sBhi + boff);
                ldmx4t(bl, sBlo + boff);
                #pragma unroll
                for (int mf = 0; mf < 2; mf++) {
                    float* d0 = &acc[(mf*8 + nf2*2)*4];
                    float* d1 = &acc[(mf*8 + nf2*2 + 1)*4];
                    mma16816(d0, ah[mf], bh[0], bh[1]);
                    mma16816(d1, ah[mf], bh[2], bh[3]);
                    mma16816(d0, ah[mf], bl[0], bl[1]);
                    mma16816(d1, ah[mf], bl[2], bl[3]);
                    mma16816(d0, al[mf], bh[0], bh[1]);
                    mma16816(d1, al[mf], bh[2], bh[3]);
                }
            }
        }
    }

    // ---- epilogue: bias + permuted-row store ----
    #pragma unroll
    for (int mf = 0; mf < 2; mf++) {
        #pragma unroll
        for (int nf = 0; nf < 8; nf++) {
            int col = n0 + wn*64 + nf*8 + tig*2;
            float b0v = bdense[col], b1v = bdense[col+1];
            float* ap = &acc[(mf*8 + nf)*4];
            int mA = m0 + wm*32 + mf*16 + g;
            if (mA < ROWS) {
                size_t ro = (size_t)((mA & 31)*TD + (mA >> 5)) * V_;
                float2 v = make_float2(ap[0] + b0v, ap[1] + b1v);
                *(float2*)(out + ro + col) = v;
            }
            int mB = mA + 8;
            if (mB < ROWS) {
                size_t ro = (size_t)((mB & 31)*TD + (mB >> 5)) * V_;
                float2 v = make_float2(ap[2] + b0v, ap[3] + b1v);
                *(float2*)(out + ro + col) = v;
            }
        }
    }
}

// ---------------- fused softmax + gate + pointer scatter. grid = 1568 rows ----------------
__global__ void __launch_bounds__(256) k_finish(float* __restrict__ out,
                                                const int* __restrict__ enc_in) {
    int r = blockIdx.x;            // r = t*32 + b
    int t = r >> 5, b = r & 31;
    float* row = out + (size_t)(b*TD + t)*V_;
    int tid = threadIdx.x;

    float m = -1e30f, s = 0.f;
    for (int v = tid*4; v < V_; v += 1024) {
        float4 x4 = *(const float4*)(row + v);
        float xs[4] = {x4.x, x4.y, x4.z, x4.w};
        #pragma unroll
        for (int i = 0; i < 4; i++) {
            float x = xs[i];
            if (x > m) { s = s*__expf(m - x) + 1.f; m = x; }
            else       { s += __expf(x - m); }
        }
    }
    __shared__ float sm[256], ss[256];
    sm[tid] = m; ss[tid] = s;
    __syncthreads();
    for (int off = 128; off; off >>= 1) {
        if (tid < off) {
            float m2 = sm[tid + off], s2 = ss[tid + off];
            float M = fmaxf(sm[tid], m2);
            ss[tid] = ss[tid]*__expf(sm[tid] - M) + s2*__expf(m2 - M);
            sm[tid] = M;
        }
        __syncthreads();
    }
    float M   = sm[0];
    float inv = 1.f / ss[0];
    float g   = g_gate[r];
    for (int v = tid*4; v < V_; v += 1024) {
        float4 x = *(const float4*)(row + v);
        x.x = g * __expf(x.x - M) * inv;
        x.y = g * __expf(x.y - M) * inv;
        x.z = g * __expf(x.z - M) * inv;
        x.w = g * __expf(x.w - M) * inv;
        *(float4*)(row + v) = x;
    }
    __syncthreads();
    if (tid < W_) {
        float beta = g_betas[r*W_ + tid];
        int tok = enc_in[b*W_ + tid];
        atomicAdd(row + tok, (1.f - g) * beta);
    }
}

// ---------------- launch ----------------
extern "C" void kernel_launch(void* const* d_in, const int* in_sizes, int n_in,
                              void* d_out, int out_size) {
    const int*   enc_in  = (const int*)d_in[0];
    const int*   dec_in  = (const int*)d_in[1];
    const float* emb     = (const float*)d_in[2];
    const float* Wf      = (const float*)d_in[3];
    const float* Uf      = (const float*)d_in[4];
    const float* bfv     = (const float*)d_in[5];
    const float* Wb      = (const float*)d_in[6];
    const float* Ub      = (const float*)d_in[7];
    const float* bbv     = (const float*)d_in[8];
    const float* Wd      = (const float*)d_in[9];
    const float* Ud      = (const float*)d_in[10];
    const float* bdv     = (const float*)d_in[11];
    const float* Wq      = (const float*)d_in[12];
    const float* Wdense  = (const float*)d_in[13];
    const float* bdense  = (const float*)d_in[14];
    const float* sentinel= (const float*)d_in[15];
    const float* a_bias  = (const float*)d_in[16];
    float* out = (float*)d_out;

    cudaFuncSetAttribute(k_dec, cudaFuncAttributeMaxDynamicSharedMemorySize, 186624);
    cudaFuncSetAttribute(k_tc_gemm, cudaFuncAttributeMaxDynamicSharedMemorySize, 106496);

    k_pre<<<dim3(298, 6), 256>>>(enc_in, dec_in, emb, Wf, bfv, Wb, bbv, Wd, bdv);

    k_split_w<<<12000, 256>>>(Wdense);

    k_enc<<<64, 192>>>(Uf, Ub);

    k_dec<<<32, 192, 186624>>>(Wq, sentinel, a_bias, Ud, Wd);

    k_split_a<<<624, 256>>>();

    k_tc_gemm<<<dim3(V_/128, MPAD/128), 256, 106496>>>(bdense, out);

    k_finish<<<ROWS, 256>>>(out, enc_in);
}